// round 6
// baseline (speedup 1.0000x reference)
#include <cuda_runtime.h>
#include <cuda_bf16.h>
#include <cstdint>

// Problem constants: N_NODES=50000, N_EDGES=640000, D=128, OUT=1
#define MAX_NODES 50000
#define D 128

__device__ float d_s1[MAX_NODES];
__device__ float d_s2[MAX_NODES];

__device__ __forceinline__ float dot4(float4 a, float4 b) {
    return a.x * b.x + a.y * b.y + a.z * b.z + a.w * b.w;
}

// Kernel 1 (unchanged from R5): s1[n]=dot(X[n],W1), s2[n]=dot(X[n],W2).
// 4 nodes/warp, fully-coalesced front-batched LDG.128 x4 (MLP_p1=4).
__global__ void node_proj_kernel(const float* __restrict__ X,
                                 const float* __restrict__ W1,
                                 const float* __restrict__ W2,
                                 int n_nodes) {
    __shared__ __align__(16) float sW1[D];
    __shared__ __align__(16) float sW2[D];
    int tid = threadIdx.x;
    if (tid < D) {
        sW1[tid] = W1[tid];
        sW2[tid] = W2[tid];
    }
    __syncthreads();

    int lane = tid & 31;
    int gwarp = (blockIdx.x * blockDim.x + tid) >> 5;
    int n0 = gwarp * 4;
    if (n0 >= n_nodes) return;

    const float4* base = reinterpret_cast<const float4*>(X) + (size_t)n0 * (D / 4) + lane;
    float4 x0 = base[0 * (D / 4)];
    float4 x1 = base[1 * (D / 4)];
    float4 x2 = base[2 * (D / 4)];
    float4 x3 = base[3 * (D / 4)];

    float4 w1v = reinterpret_cast<const float4*>(sW1)[lane];
    float4 w2v = reinterpret_cast<const float4*>(sW2)[lane];

    float a0 = dot4(x0, w1v), b0 = dot4(x0, w2v);
    float a1 = dot4(x1, w1v), b1 = dot4(x1, w2v);
    float a2 = dot4(x2, w1v), b2 = dot4(x2, w2v);
    float a3 = dot4(x3, w1v), b3 = dot4(x3, w2v);

    #pragma unroll
    for (int off = 16; off > 0; off >>= 1) {
        a0 += __shfl_xor_sync(0xFFFFFFFF, a0, off);
        b0 += __shfl_xor_sync(0xFFFFFFFF, b0, off);
        a1 += __shfl_xor_sync(0xFFFFFFFF, a1, off);
        b1 += __shfl_xor_sync(0xFFFFFFFF, b1, off);
        a2 += __shfl_xor_sync(0xFFFFFFFF, a2, off);
        b2 += __shfl_xor_sync(0xFFFFFFFF, b2, off);
        a3 += __shfl_xor_sync(0xFFFFFFFF, a3, off);
        b3 += __shfl_xor_sync(0xFFFFFFFF, b3, off);
    }

    if (lane == 0) {
        d_s1[n0]     = a0;  d_s2[n0]     = b0;
        if (n0 + 1 < n_nodes) { d_s1[n0 + 1] = a1;  d_s2[n0 + 1] = b1; }
        if (n0 + 2 < n_nodes) { d_s1[n0 + 2] = a2;  d_s2[n0 + 2] = b2; }
        if (n0 + 3 < n_nodes) { d_s1[n0 + 3] = a3;  d_s2[n0 + 3] = b3; }
    }
}

#define CLAMP(v) min(max((v), 0), MAX_NODES - 1)

// Kernel 2: one block per SM, s1 table cached in SMEM (195.3 KB dynamic).
// s1 gathers go through the smem crossbar (LDS pipe); s2 gathers through
// L1tex/L2 — the two pipes run in parallel, halving L1tex wavefronts.
__global__ void edge_kernel_smem(const int* __restrict__ ei,
                                 float* __restrict__ out,
                                 int n_edges) {
    extern __shared__ float s_s1[];

    // Fill: copy whole s1 table into smem (12500 float4s, coalesced).
    float4* dst = reinterpret_cast<float4*>(s_s1);
    const float4* src = reinterpret_cast<const float4*>(d_s1);
    #pragma unroll 4
    for (int i = threadIdx.x; i < MAX_NODES / 4; i += blockDim.x)
        dst[i] = src[i];
    __syncthreads();

    // This block's contiguous edge range.
    int chunk = (n_edges + gridDim.x - 1) / gridDim.x;
    int start = blockIdx.x * chunk;
    int end = min(start + chunk, n_edges);

    int tid = threadIdx.x;
    int nthr = blockDim.x;

    // 4-way unrolled strided loop: batch index loads, then gathers, then stores.
    int e = start + tid;
    for (; e + 3 * nthr < end; e += 4 * nthr) {
        int sA = ei[e];            int dA = ei[n_edges + e];
        int sB = ei[e + nthr];     int dB = ei[n_edges + e + nthr];
        int sC = ei[e + 2 * nthr]; int dC = ei[n_edges + e + 2 * nthr];
        int sD = ei[e + 3 * nthr]; int dD = ei[n_edges + e + 3 * nthr];

        float g2A = __ldg(&d_s2[CLAMP(dA)]);
        float g2B = __ldg(&d_s2[CLAMP(dB)]);
        float g2C = __ldg(&d_s2[CLAMP(dC)]);
        float g2D = __ldg(&d_s2[CLAMP(dD)]);

        float g1A = s_s1[CLAMP(sA)];
        float g1B = s_s1[CLAMP(sB)];
        float g1C = s_s1[CLAMP(sC)];
        float g1D = s_s1[CLAMP(sD)];

        out[e]            = g1A + g2A;
        out[e + nthr]     = g1B + g2B;
        out[e + 2 * nthr] = g1C + g2C;
        out[e + 3 * nthr] = g1D + g2D;
    }
    for (; e < end; e += nthr) {
        int s = CLAMP(ei[e]);
        int d = CLAMP(ei[n_edges + e]);
        out[e] = s_s1[s] + __ldg(&d_s2[d]);
    }
}

extern "C" void kernel_launch(void* const* d_in, const int* in_sizes, int n_in,
                              void* d_out, int out_size) {
    const float* X  = (const float*)d_in[0];
    const int*   ei = (const int*)d_in[1];     // [2, E] int32
    const float* W1 = (const float*)d_in[2];
    const float* W2 = (const float*)d_in[3];
    float* out = (float*)d_out;

    int n_nodes = in_sizes[0] / D;             // 50000
    int n_edges = in_sizes[1] / 2;             // 640000

    // Kernel 1: 4 nodes/warp, 256 threads/block = 32 nodes/block
    int threads1 = 256;
    int blocks1 = (n_nodes + 31) / 32;
    node_proj_kernel<<<blocks1, threads1>>>(X, W1, W2, n_nodes);

    // Kernel 2: one block per SM, s1 table in dynamic smem.
    static int n_sms = 0;
    if (n_sms == 0) {
        cudaDeviceGetAttribute(&n_sms, cudaDevAttrMultiProcessorCount, 0);
        if (n_sms <= 0) n_sms = 148;
        cudaFuncSetAttribute(edge_kernel_smem,
                             cudaFuncAttributeMaxDynamicSharedMemorySize,
                             MAX_NODES * (int)sizeof(float));
    }
    size_t smem = MAX_NODES * sizeof(float);   // 200000 B
    edge_kernel_smem<<<n_sms, 1024, smem>>>(ei, out, n_edges);
}

// round 8
// speedup vs baseline: 1.4231x; 1.4231x over previous
#include <cuda_runtime.h>
#include <cuda_fp16.h>
#include <cuda_bf16.h>
#include <cstdint>

// Problem constants: N_NODES=50000, N_EDGES=640000, D=128, OUT=1
#define MAX_NODES 50000
#define D 128

// Packed per-node projections: lo = dot(X[n],W1), hi = dot(X[n],W2), fp16.
// 200 KB total -> fits entirely in one SM's shared memory for the edge kernel.
__device__ __half2 d_pack[MAX_NODES];

__device__ __forceinline__ float dot4(float4 a, float4 b) {
    return a.x * b.x + a.y * b.y + a.z * b.z + a.w * b.w;
}

// Kernel 1: 8 rows per warp, 8 lanes per row.
// Every LDG.128 is a full-warp coalesced load of 4 complete 128B lines;
// 8 loads front-batched (MLP_p1=8). 3 shuffle levels per reduction.
__global__ void node_proj_kernel(const float* __restrict__ X,
                                 const float* __restrict__ W1,
                                 const float* __restrict__ W2,
                                 int n_nodes) {
    __shared__ __align__(16) float sW1[D];
    __shared__ __align__(16) float sW2[D];
    int tid = threadIdx.x;
    if (tid < D) {
        sW1[tid] = W1[tid];
        sW2[tid] = W2[tid];
    }
    __syncthreads();

    int lane = tid & 31;
    int sub  = lane & 7;     // lane within 8-lane row group
    int grp  = lane >> 3;    // row group 0..3
    int gwarp = (blockIdx.x * blockDim.x + tid) >> 5;
    int n0 = gwarp * 8;
    if (n0 >= n_nodes) return;   // 50000 % 8 == 0 -> whole warps only

    int rowA = n0 + grp;
    int rowB = n0 + 4 + grp;

    const float4* Xv = reinterpret_cast<const float4*>(X);
    float4 a0 = Xv[(size_t)rowA * 32 + sub + 0];
    float4 a1 = Xv[(size_t)rowA * 32 + sub + 8];
    float4 a2 = Xv[(size_t)rowA * 32 + sub + 16];
    float4 a3 = Xv[(size_t)rowA * 32 + sub + 24];
    float4 b0 = Xv[(size_t)rowB * 32 + sub + 0];
    float4 b1 = Xv[(size_t)rowB * 32 + sub + 8];
    float4 b2 = Xv[(size_t)rowB * 32 + sub + 16];
    float4 b3 = Xv[(size_t)rowB * 32 + sub + 24];

    const float4* w1 = reinterpret_cast<const float4*>(sW1);
    const float4* w2 = reinterpret_cast<const float4*>(sW2);
    float4 w1_0 = w1[sub], w1_1 = w1[sub + 8], w1_2 = w1[sub + 16], w1_3 = w1[sub + 24];
    float4 w2_0 = w2[sub], w2_1 = w2[sub + 8], w2_2 = w2[sub + 16], w2_3 = w2[sub + 24];

    float sA1 = dot4(a0, w1_0) + dot4(a1, w1_1) + dot4(a2, w1_2) + dot4(a3, w1_3);
    float sA2 = dot4(a0, w2_0) + dot4(a1, w2_1) + dot4(a2, w2_2) + dot4(a3, w2_3);
    float sB1 = dot4(b0, w1_0) + dot4(b1, w1_1) + dot4(b2, w1_2) + dot4(b3, w1_3);
    float sB2 = dot4(b0, w2_0) + dot4(b1, w2_1) + dot4(b2, w2_2) + dot4(b3, w2_3);

    #pragma unroll
    for (int off = 4; off > 0; off >>= 1) {
        sA1 += __shfl_xor_sync(0xFFFFFFFF, sA1, off);
        sA2 += __shfl_xor_sync(0xFFFFFFFF, sA2, off);
        sB1 += __shfl_xor_sync(0xFFFFFFFF, sB1, off);
        sB2 += __shfl_xor_sync(0xFFFFFFFF, sB2, off);
    }

    if (sub == 0) {
        d_pack[rowA] = __floats2half2_rn(sA1, sA2);
        d_pack[rowB] = __floats2half2_rn(sB1, sB2);
    }
}

#define CLAMP(v) min(max((v), 0), MAX_NODES - 1)

// Kernel 2: whole packed table (200 KB) in shared memory.
// Both gathers are LDS (smem crossbar) -> zero L1tex gather replays.
__global__ void edge_kernel_pack(const int* __restrict__ ei,
                                 float* __restrict__ out,
                                 int n_edges) {
    extern __shared__ __half2 s_p[];

    // Fill: 50000 half2 = 200000 B = 12500 uint4 (4 half2 per uint4).
    // (R7 bug: used MAX_NODES/8 and left half the table uninitialized.)
    {
        uint4* dst = reinterpret_cast<uint4*>(s_p);
        const uint4* src = reinterpret_cast<const uint4*>(d_pack);
        for (int i = threadIdx.x; i < MAX_NODES / 4; i += blockDim.x)
            dst[i] = src[i];
    }
    __syncthreads();

    // Quad-based chunking: each thread handles 4 consecutive edges (int4 loads).
    int total_quads = n_edges >> 2;                 // 160000 (E % 4 == 0)
    int qpb = (total_quads + gridDim.x - 1) / gridDim.x;
    int q_start = blockIdx.x * qpb;
    int q_end = min(q_start + qpb, total_quads);

    for (int q = q_start + threadIdx.x; q < q_end; q += blockDim.x) {
        int e0 = q * 4;
        int4 s4 = *reinterpret_cast<const int4*>(ei + e0);
        int4 d4 = *reinterpret_cast<const int4*>(ei + n_edges + e0);

        __half2 px = s_p[CLAMP(s4.x)], qx = s_p[CLAMP(d4.x)];
        __half2 py = s_p[CLAMP(s4.y)], qy = s_p[CLAMP(d4.y)];
        __half2 pz = s_p[CLAMP(s4.z)], qz = s_p[CLAMP(d4.z)];
        __half2 pw = s_p[CLAMP(s4.w)], qw = s_p[CLAMP(d4.w)];

        float4 r;
        r.x = __low2float(px) + __high2float(qx);
        r.y = __low2float(py) + __high2float(qy);
        r.z = __low2float(pz) + __high2float(qz);
        r.w = __low2float(pw) + __high2float(qw);
        *reinterpret_cast<float4*>(out + e0) = r;
    }

    // Scalar tail (n_edges % 4 != 0) — block 0 only.
    if (blockIdx.x == 0) {
        for (int e = total_quads * 4 + threadIdx.x; e < n_edges; e += blockDim.x) {
            int s = CLAMP(ei[e]);
            int d = CLAMP(ei[n_edges + e]);
            out[e] = __low2float(s_p[s]) + __high2float(s_p[d]);
        }
    }
}

extern "C" void kernel_launch(void* const* d_in, const int* in_sizes, int n_in,
                              void* d_out, int out_size) {
    const float* X  = (const float*)d_in[0];
    const int*   ei = (const int*)d_in[1];     // [2, E] int32
    const float* W1 = (const float*)d_in[2];
    const float* W2 = (const float*)d_in[3];
    float* out = (float*)d_out;

    int n_nodes = in_sizes[0] / D;             // 50000
    int n_edges = in_sizes[1] / 2;             // 640000

    static int n_sms = 0;
    if (n_sms == 0) {
        cudaDeviceGetAttribute(&n_sms, cudaDevAttrMultiProcessorCount, 0);
        if (n_sms <= 0) n_sms = 148;
        cudaFuncSetAttribute(edge_kernel_pack,
                             cudaFuncAttributeMaxDynamicSharedMemorySize,
                             MAX_NODES * (int)sizeof(__half2));
    }

    // Kernel 1: 8 rows/warp, 256 threads/block = 64 rows/block
    int threads1 = 256;
    int blocks1 = (n_nodes + 63) / 64;
    node_proj_kernel<<<blocks1, threads1>>>(X, W1, W2, n_nodes);

    // Kernel 2: one block per SM, packed table in smem.
    size_t smem = MAX_NODES * sizeof(__half2);   // 200000 B
    edge_kernel_pack<<<n_sms, 1024, smem>>>(ei, out, n_edges);
}

// round 9
// speedup vs baseline: 1.7672x; 1.2418x over previous
#include <cuda_runtime.h>
#include <cuda_fp16.h>
#include <cuda_bf16.h>
#include <cstdint>

// Problem constants: N_NODES=50000, N_EDGES=640000, D=128, OUT=1
#define MAX_NODES 50000
#define D 128
#define TABLE_BYTES (MAX_NODES * 4)   // 200000 B of __half2
#define FILL_CHUNK 50000              // 4 chunks, each multiple of 16

// Packed per-node projections: lo = dot(X[n],W1), hi = dot(X[n],W2), fp16.
__device__ __align__(16) __half2 d_pack[MAX_NODES];

__device__ __forceinline__ float dot4(float4 a, float4 b) {
    return a.x * b.x + a.y * b.y + a.z * b.z + a.w * b.w;
}

// Kernel 1 (unchanged from R8): 8 rows/warp, 8 lanes/row, fully-coalesced
// front-batched LDG.128 x8, 3-level group reduction.
__global__ void node_proj_kernel(const float* __restrict__ X,
                                 const float* __restrict__ W1,
                                 const float* __restrict__ W2,
                                 int n_nodes) {
    __shared__ __align__(16) float sW1[D];
    __shared__ __align__(16) float sW2[D];
    int tid = threadIdx.x;
    if (tid < D) {
        sW1[tid] = W1[tid];
        sW2[tid] = W2[tid];
    }
    __syncthreads();

    int lane = tid & 31;
    int sub  = lane & 7;
    int grp  = lane >> 3;
    int gwarp = (blockIdx.x * blockDim.x + tid) >> 5;
    int n0 = gwarp * 8;
    if (n0 >= n_nodes) return;

    int rowA = n0 + grp;
    int rowB = n0 + 4 + grp;

    const float4* Xv = reinterpret_cast<const float4*>(X);
    float4 a0 = Xv[(size_t)rowA * 32 + sub + 0];
    float4 a1 = Xv[(size_t)rowA * 32 + sub + 8];
    float4 a2 = Xv[(size_t)rowA * 32 + sub + 16];
    float4 a3 = Xv[(size_t)rowA * 32 + sub + 24];
    float4 b0 = Xv[(size_t)rowB * 32 + sub + 0];
    float4 b1 = Xv[(size_t)rowB * 32 + sub + 8];
    float4 b2 = Xv[(size_t)rowB * 32 + sub + 16];
    float4 b3 = Xv[(size_t)rowB * 32 + sub + 24];

    const float4* w1 = reinterpret_cast<const float4*>(sW1);
    const float4* w2 = reinterpret_cast<const float4*>(sW2);
    float4 w1_0 = w1[sub], w1_1 = w1[sub + 8], w1_2 = w1[sub + 16], w1_3 = w1[sub + 24];
    float4 w2_0 = w2[sub], w2_1 = w2[sub + 8], w2_2 = w2[sub + 16], w2_3 = w2[sub + 24];

    float sA1 = dot4(a0, w1_0) + dot4(a1, w1_1) + dot4(a2, w1_2) + dot4(a3, w1_3);
    float sA2 = dot4(a0, w2_0) + dot4(a1, w2_1) + dot4(a2, w2_2) + dot4(a3, w2_3);
    float sB1 = dot4(b0, w1_0) + dot4(b1, w1_1) + dot4(b2, w1_2) + dot4(b3, w1_3);
    float sB2 = dot4(b0, w2_0) + dot4(b1, w2_1) + dot4(b2, w2_2) + dot4(b3, w2_3);

    #pragma unroll
    for (int off = 4; off > 0; off >>= 1) {
        sA1 += __shfl_xor_sync(0xFFFFFFFF, sA1, off);
        sA2 += __shfl_xor_sync(0xFFFFFFFF, sA2, off);
        sB1 += __shfl_xor_sync(0xFFFFFFFF, sB1, off);
        sB2 += __shfl_xor_sync(0xFFFFFFFF, sB2, off);
    }

    if (sub == 0) {
        d_pack[rowA] = __floats2half2_rn(sA1, sA2);
        d_pack[rowB] = __floats2half2_rn(sB1, sB2);
    }
}

#define CLAMP(v) min(max((v), 0), MAX_NODES - 1)

// Kernel 2: table brought in with cp.async.bulk (HW bulk engine, no per-thread
// load chains); edge indices prefetched into registers BEFORE the mbarrier
// wait so their global latency overlaps the fill. Gathers are pure LDS.
__global__ void edge_kernel_pack(const int* __restrict__ ei,
                                 float* __restrict__ out,
                                 int n_edges) {
    extern __shared__ __align__(16) unsigned char smem_raw[];
    __half2* s_p = reinterpret_cast<__half2*>(smem_raw);

    uint32_t smem_base;
    asm("{ .reg .u64 t; cvta.to.shared.u64 t, %1; cvt.u32.u64 %0, t; }"
        : "=r"(smem_base) : "l"(smem_raw));
    uint32_t mbar = smem_base + TABLE_BYTES;

    int tid = threadIdx.x;

    if (tid == 0) {
        asm volatile("mbarrier.init.shared.b64 [%0], 1;" :: "r"(mbar) : "memory");
    }
    __syncthreads();

    if (tid == 0) {
        asm volatile("mbarrier.arrive.expect_tx.shared.b64 _, [%0], %1;"
                     :: "r"(mbar), "r"((uint32_t)TABLE_BYTES) : "memory");
        const char* src = reinterpret_cast<const char*>(d_pack);
        #pragma unroll
        for (int c = 0; c < 4; c++) {
            asm volatile(
                "cp.async.bulk.shared::cta.global.mbarrier::complete_tx::bytes "
                "[%0], [%1], %2, [%3];"
                :: "r"(smem_base + c * FILL_CHUNK), "l"(src + (size_t)c * FILL_CHUNK),
                   "r"((uint32_t)FILL_CHUNK), "r"(mbar) : "memory");
        }
    }

    // ---- Prefetch edge indices (overlaps the bulk fill) ----
    int total_quads = n_edges >> 2;                   // 160000
    int qpb = (total_quads + gridDim.x - 1) / gridDim.x;
    int q_start = blockIdx.x * qpb;
    int q_end = min(q_start + qpb, total_quads);

    int q0 = q_start + tid;
    int q1 = q0 + blockDim.x;
    bool v0 = q0 < q_end;
    bool v1 = q1 < q_end;

    int4 s4a = make_int4(0, 0, 0, 0), d4a = s4a, s4b = s4a, d4b = s4a;
    if (v0) {
        s4a = *reinterpret_cast<const int4*>(ei + q0 * 4);
        d4a = *reinterpret_cast<const int4*>(ei + n_edges + q0 * 4);
    }
    if (v1) {
        s4b = *reinterpret_cast<const int4*>(ei + q1 * 4);
        d4b = *reinterpret_cast<const int4*>(ei + n_edges + q1 * 4);
    }

    // ---- Wait for the table ----
    {
        uint32_t done;
        asm volatile(
            "{\n\t"
            ".reg .pred p;\n\t"
            "mbarrier.try_wait.parity.acquire.cta.shared::cta.b64 p, [%1], 0;\n\t"
            "selp.b32 %0, 1, 0, p;\n\t"
            "}"
            : "=r"(done) : "r"(mbar) : "memory");
        if (!done) {
            asm volatile(
                "{\n\t"
                ".reg .pred P1;\n\t"
                "WL_%=:\n\t"
                "mbarrier.try_wait.parity.acquire.cta.shared::cta.b64 P1, [%0], 0, 0x989680;\n\t"
                "@P1 bra.uni WD_%=;\n\t"
                "bra.uni WL_%=;\n\t"
                "WD_%=:\n\t"
                "}"
                :: "r"(mbar) : "memory");
        }
    }

    // ---- Gather + store ----
    if (v0) {
        float4 r;
        r.x = __low2float(s_p[CLAMP(s4a.x)]) + __high2float(s_p[CLAMP(d4a.x)]);
        r.y = __low2float(s_p[CLAMP(s4a.y)]) + __high2float(s_p[CLAMP(d4a.y)]);
        r.z = __low2float(s_p[CLAMP(s4a.z)]) + __high2float(s_p[CLAMP(d4a.z)]);
        r.w = __low2float(s_p[CLAMP(s4a.w)]) + __high2float(s_p[CLAMP(d4a.w)]);
        *reinterpret_cast<float4*>(out + q0 * 4) = r;
    }
    if (v1) {
        float4 r;
        r.x = __low2float(s_p[CLAMP(s4b.x)]) + __high2float(s_p[CLAMP(d4b.x)]);
        r.y = __low2float(s_p[CLAMP(s4b.y)]) + __high2float(s_p[CLAMP(d4b.y)]);
        r.z = __low2float(s_p[CLAMP(s4b.z)]) + __high2float(s_p[CLAMP(d4b.z)]);
        r.w = __low2float(s_p[CLAMP(s4b.w)]) + __high2float(s_p[CLAMP(d4b.w)]);
        *reinterpret_cast<float4*>(out + q1 * 4) = r;
    }

    // Scalar tail (n_edges % 4 != 0) — block 0 only.
    if (blockIdx.x == 0) {
        for (int e = total_quads * 4 + tid; e < n_edges; e += blockDim.x) {
            int s = CLAMP(ei[e]);
            int d = CLAMP(ei[n_edges + e]);
            out[e] = __low2float(s_p[s]) + __high2float(s_p[d]);
        }
    }
}

extern "C" void kernel_launch(void* const* d_in, const int* in_sizes, int n_in,
                              void* d_out, int out_size) {
    const float* X  = (const float*)d_in[0];
    const int*   ei = (const int*)d_in[1];     // [2, E] int32
    const float* W1 = (const float*)d_in[2];
    const float* W2 = (const float*)d_in[3];
    float* out = (float*)d_out;

    int n_nodes = in_sizes[0] / D;             // 50000
    int n_edges = in_sizes[1] / 2;             // 640000

    static int n_sms = 0;
    if (n_sms == 0) {
        cudaDeviceGetAttribute(&n_sms, cudaDevAttrMultiProcessorCount, 0);
        if (n_sms <= 0) n_sms = 148;
        cudaFuncSetAttribute(edge_kernel_pack,
                             cudaFuncAttributeMaxDynamicSharedMemorySize,
                             TABLE_BYTES + 16);
    }

    // Kernel 1: 8 rows/warp, 256 threads/block = 64 rows/block
    int threads1 = 256;
    int blocks1 = (n_nodes + 63) / 64;
    node_proj_kernel<<<blocks1, threads1>>>(X, W1, W2, n_nodes);

    // Kernel 2: one block per SM; table (200000 B) + mbarrier (16 B) in smem.
    size_t smem = TABLE_BYTES + 16;
    edge_kernel_pack<<<n_sms, 1024, smem>>>(ei, out, n_edges);
}